// round 4
// baseline (speedup 1.0000x reference)
#include <cuda_runtime.h>
#include <math.h>

#define BATCH   16384
#define TSTEPS  300
#define NBASIS  32
#define HID     64
#define DTC     (1.0f/300.0f)
#define BPB     64               // batches per block
#define THREADS 128              // 1 thread = 1 channel (batch, dim)
#define NBLOCKS (BATCH/BPB)      // 256

#define OFF_SIG ((size_t)BATCH*2*TSTEPS)
#define OFF_VAL (OFF_SIG + (size_t)BATCH*2)

// ---- shared memory layout (floats) ----
#define SH_XR    0                    // 608 : (x_k, rdt_k) float2 table, 300 entries
#define SH_HT    (SH_XR + 608)        // 4096: hidden transposed [64][64]
#define SH_WD    (SH_HT + 4096)       // 192 : w2 rows 0,1,65
#define SH_SW    (SH_WD + 192)        // 128
#define SH_VW    (SH_SW + 128)        // 128
#define SH_Q     (SH_VW + 128)        // 640 : poly-coeff map [d][m][k]
#define SH_P     (SH_Q + 640)         // 160 : P[m][j] basis->poly
#define SH_B     (SH_P + 160)         // 24  : 0,1:b2g 2:b2az 3,4:sb 5,6:vb 7..11:S0-4 12..21:C
#define SH_F1W   (SH_B + 24)          // 192
#define SH_F1B   (SH_F1W + 192)       // 64
#define SH_V     (SH_F1B + 64)        // 128
#define SH_TR    (SH_V + 128)         // 3968: 4 warps x [32][31]
#define SH_TOTAL (SH_TR + 3968)       // 10328 floats = 41312 bytes

extern "C" __global__ void __launch_bounds__(THREADS)
ndp_kernel(const float* __restrict__ state,
           const float* __restrict__ fc1w, const float* __restrict__ fc1b,
           const float* __restrict__ w2,   const float* __restrict__ b2,
           const float* __restrict__ sw,   const float* __restrict__ sb,
           const float* __restrict__ vw,   const float* __restrict__ vb,
           const float* __restrict__ dc,   const float* __restrict__ ds2,
           float* __restrict__ out)
{
    extern __shared__ float sm[];
    const int tid  = threadIdx.x;
    const int bk   = blockIdx.x;
    const int lane = tid & 31;
    const int warp = tid >> 5;

    // ---- stage small weights ----
    for (int i = tid; i < 128; i += THREADS) sm[SH_WD + i] = w2[i];               // rows 0,1
    for (int i = tid; i < 64;  i += THREADS) sm[SH_WD + 128 + i] = w2[65*HID + i];// row 65
    for (int i = tid; i < 128; i += THREADS) { sm[SH_SW + i] = sw[i]; sm[SH_VW + i] = vw[i]; }
    for (int i = tid; i < 192; i += THREADS) sm[SH_F1W + i] = fc1w[i];
    for (int i = tid; i < 64;  i += THREADS) sm[SH_F1B + i] = fc1b[i];
    if (tid == 0) {
        sm[SH_B + 0] = b2[0]; sm[SH_B + 1] = b2[1]; sm[SH_B + 2] = b2[65];
        sm[SH_B + 3] = sb[0]; sm[SH_B + 4] = sb[1];
        sm[SH_B + 5] = vb[0]; sm[SH_B + 6] = vb[1];
    }
    // ---- P[m][j]: 2nd-order Taylor of exp RBF -> quartic basis (warp 0) ----
    // psi_j(x) ~= 1 - e + e^2/2, e = a(x-c)^2 <= 1.1e-3 (truncation ~2e-10)
    if (warp == 0) {
        float c  = dc[lane], s2 = ds2[lane];
        float a  = 0.5f / s2, a2 = a*a, c2 = c*c;
        float p0 = 1.0f - a*c2 + 0.5f*a2*c2*c2;
        float p1 = 2.0f*a*c - 2.0f*a2*c2*c;
        float p2 = -a + 3.0f*a2*c2;
        float p3 = -2.0f*a2*c;
        float p4 = 0.5f*a2;
        sm[SH_P + 0*32 + lane] = p0;
        sm[SH_P + 1*32 + lane] = p1;
        sm[SH_P + 2*32 + lane] = p2;
        sm[SH_P + 3*32 + lane] = p3;
        sm[SH_P + 4*32 + lane] = p4;
        // S_m = sum_j P[m][j]  (quartic coeffs of the psi-sum normalizer)
        #pragma unroll
        for (int o = 16; o; o >>= 1) {
            p0 += __shfl_xor_sync(0xffffffffu, p0, o);
            p1 += __shfl_xor_sync(0xffffffffu, p1, o);
            p2 += __shfl_xor_sync(0xffffffffu, p2, o);
            p3 += __shfl_xor_sync(0xffffffffu, p3, o);
            p4 += __shfl_xor_sync(0xffffffffu, p4, o);
        }
        if (lane == 0) {
            sm[SH_B + 7]  = p0; sm[SH_B + 8]  = p1; sm[SH_B + 9] = p2;
            sm[SH_B + 10] = p3; sm[SH_B + 11] = p4;
        }
    }
    __syncthreads();

    // ---- fc1 hidden layer, transposed [64 hid][64 batch] ----
    {
        int bb = tid & 63;
        int gb = bk*BPB + bb;
        float s0 = state[gb*3+0], s1 = state[gb*3+1], s2v = state[gb*3+2];
        for (int hh = (tid >> 6); hh < HID; hh += 2) {
            float v = sm[SH_F1W + hh*3+0]*s0 + sm[SH_F1W + hh*3+1]*s1
                    + sm[SH_F1W + hh*3+2]*s2v + sm[SH_F1B + hh];
            sm[SH_HT + hh*64 + bb] = tanhf(v) * 0.1f;
        }
    }
    // ---- (x_k, rdt_k) table: x = (1-DT)^(k+1), rdt = DT*x / S(x) ----
    {
        float S0 = sm[SH_B+7], S1 = sm[SH_B+8], S2 = sm[SH_B+9],
              S3 = sm[SH_B+10], S4 = sm[SH_B+11];
        float l2 = log2f(1.0f - DTC);
        for (int k = tid; k < TSTEPS; k += THREADS) {
            float x = exp2f((float)(k + 1) * l2);
            float S = __fmaf_rn(__fmaf_rn(__fmaf_rn(__fmaf_rn(S4,x,S3),x,S2),x,S1),x,S0);
            sm[SH_XR + 2*k]     = x;
            sm[SH_XR + 2*k + 1] = __fdividef(x * DTC, S);
        }
    }
    // ---- Q[d][m][k] = sum_j w2[(2+32d+j)*64+k] * P[m][j] ----
    for (int o = tid; o < 2*5*HID; o += THREADS) {
        int k = o & 63;
        int m = (o >> 6) % 5;
        int d = o / (5*HID);
        const float* wr = w2 + (2 + d*32)*HID + k;
        float acc = 0.0f;
        #pragma unroll 8
        for (int j = 0; j < NBASIS; j++)
            acc += wr[j*HID] * sm[SH_P + m*32 + j];
        sm[SH_Q + o] = acc;
    }
    // ---- C[d*5+m] = sum_j b2[2+32d+j] * P[m][j] ----
    if (tid < 10) {
        int d = tid / 5, m = tid % 5;
        float acc = 0.0f;
        for (int j = 0; j < NBASIS; j++)
            acc += b2[2 + d*32 + j] * sm[SH_P + m*32 + j];
        sm[SH_B + 12 + tid] = acc;
    }
    __syncthreads();

    // ---- per-channel GEMV ----
    const int b  = tid >> 1;
    const int d  = tid & 1;
    const int gb = bk*BPB + b;

    float goal = sm[SH_B + d];
    float azv  = sm[SH_B + 2];
    float sgp  = sm[SH_B + 3 + d];
    float vlp  = sm[SH_B + 5 + d];
    float c0 = sm[SH_B + 12 + d*5 + 0], c1 = sm[SH_B + 12 + d*5 + 1];
    float c2 = sm[SH_B + 12 + d*5 + 2], c3 = sm[SH_B + 12 + d*5 + 3];
    float c4 = sm[SH_B + 12 + d*5 + 4];

    #pragma unroll
    for (int k = 0; k < HID; k += 4) {
        float h0 = sm[SH_HT + (k+0)*64 + b];
        float h1 = sm[SH_HT + (k+1)*64 + b];
        float h2 = sm[SH_HT + (k+2)*64 + b];
        float h3 = sm[SH_HT + (k+3)*64 + b];
        float4 wg = *(const float4*)(sm + SH_WD + d*64 + k);
        goal += h0*wg.x + h1*wg.y + h2*wg.z + h3*wg.w;
        float4 wa = *(const float4*)(sm + SH_WD + 128 + k);
        azv  += h0*wa.x + h1*wa.y + h2*wa.z + h3*wa.w;
        float4 ws = *(const float4*)(sm + SH_SW + d*64 + k);
        sgp  += h0*ws.x + h1*ws.y + h2*ws.z + h3*ws.w;
        float4 wvv = *(const float4*)(sm + SH_VW + d*64 + k);
        vlp  += h0*wvv.x + h1*wvv.y + h2*wvv.z + h3*wvv.w;
        float4 q;
        q = *(const float4*)(sm + SH_Q + (d*5+0)*64 + k);
        c0 += h0*q.x + h1*q.y + h2*q.z + h3*q.w;
        q = *(const float4*)(sm + SH_Q + (d*5+1)*64 + k);
        c1 += h0*q.x + h1*q.y + h2*q.z + h3*q.w;
        q = *(const float4*)(sm + SH_Q + (d*5+2)*64 + k);
        c2 += h0*q.x + h1*q.y + h2*q.z + h3*q.w;
        q = *(const float4*)(sm + SH_Q + (d*5+3)*64 + k);
        c3 += h0*q.x + h1*q.y + h2*q.z + h3*q.w;
        q = *(const float4*)(sm + SH_Q + (d*5+4)*64 + k);
        c4 += h0*q.x + h1*q.y + h2*q.z + h3*q.w;
    }

    azv = fminf(fmaxf(azv, 0.5f), 30.0f);
    out[OFF_SIG + (size_t)bk*THREADS + tid] = 1.0f / (1.0f + expf(-sgp)) + 0.001f;
    sm[SH_V + tid] = vlp;

    const float y0 = state[gb*3 + d];
    const float G  = goal - y0;
    c0 *= G; c1 *= G; c2 *= G; c3 *= G; c4 *= G;

    // recurrence constants: z' = K1*z + (Pg - P1*y + f*rdt)
    const float bz  = azv * 0.25f;
    const float P1  = DTC * azv * bz;
    const float Pg  = P1 * goal;
    const float nP1 = -P1;
    const float K1  = 1.0f - DTC * azv;

    // ---- DMP Euler rollout ----
    float y = y0, z = 0.01f;
    float* trb   = sm + SH_TR + warp*(32*31);
    float* out_a = out + (size_t)bk*THREADS*TSTEPS;
    const float2* xr = (const float2*)(sm + SH_XR);

    for (int ch = 0; ch < 10; ch++) {
        #pragma unroll 6
        for (int s = 0; s < 30; s++) {
            float2 xv = xr[ch*30 + s];                 // broadcast LDS.64
            float h = __fmaf_rn(__fmaf_rn(__fmaf_rn(__fmaf_rn(c4, xv.x, c3),
                                                    xv.x, c2), xv.x, c1), xv.x, c0);
            float u = __fmaf_rn(h, xv.y, Pg);
            u = __fmaf_rn(nP1, y, u);                  // uses OLD y
            float inc  = __fmul_rn(z, DTC);            // exact output quantization
            float ynew = __fadd_rn(y, inc);
            trb[lane*31 + s] = ynew - y;               // Sterbenz-exact a[t]
            z = __fmaf_rn(K1, z, u);                   // uses OLD z
            y = ynew;
        }
        __syncwarp();
        int t0 = ch*30;
        #pragma unroll
        for (int i = 0; i < 32; i++) {
            if (lane < 30)
                out_a[(size_t)(warp*32 + i)*TSTEPS + t0 + lane] = trb[i*31 + lane];
        }
        __syncwarp();
    }

    // ---- value broadcast fill: per-warp, fully coalesced float4 ----
    float* out_v = out + OFF_VAL + (size_t)bk*THREADS*TSTEPS;
    #pragma unroll 4
    for (int c = 0; c < 32; c++) {
        float v = sm[SH_V + warp*32 + c];
        float4 vv = make_float4(v, v, v, v);
        float* base = out_v + (size_t)(warp*32 + c)*TSTEPS;
        *(float4*)(base + 4*lane)        = vv;
        *(float4*)(base + 4*(32 + lane)) = vv;
        if (lane < 11) *(float4*)(base + 4*(64 + lane)) = vv;   // 75 = 32+32+11
    }
}

extern "C" void kernel_launch(void* const* d_in, const int* in_sizes, int n_in,
                              void* d_out, int out_size)
{
    (void)in_sizes; (void)n_in; (void)out_size;
    ndp_kernel<<<NBLOCKS, THREADS, SH_TOTAL * sizeof(float)>>>(
        (const float*)d_in[0],  (const float*)d_in[1], (const float*)d_in[2],
        (const float*)d_in[3],  (const float*)d_in[4], (const float*)d_in[5],
        (const float*)d_in[6],  (const float*)d_in[7], (const float*)d_in[8],
        (const float*)d_in[9],  (const float*)d_in[10], (float*)d_out);
}